// round 1
// baseline (speedup 1.0000x reference)
#include <cuda_runtime.h>

// HybridReducedQ: quantum circuit reduces analytically to
//   q = cos(x_q[:,1] + p[1]) * cos(x_q[:,2] + p[2])
// followed by MLP: relu(W1@[q,x_c]+b1) -> relu(W2@h1+b2) -> W3@h2+b3.
//
// Strategy: fp32x2 packed FMAs (full-rate fp32 on Blackwell), output-pair
// packing with transposed weights in shared, coalesced x_c staging.

#define ROWS_PER_BLOCK 128
#define NTHREADS 128

__device__ __forceinline__ unsigned long long ffma2(unsigned long long a,
                                                    unsigned long long b,
                                                    unsigned long long c) {
    unsigned long long d;
    asm("fma.rn.f32x2 %0, %1, %2, %3;" : "=l"(d) : "l"(a), "l"(b), "l"(c));
    return d;
}
__device__ __forceinline__ unsigned long long pack2(float lo, float hi) {
    unsigned long long d;
    asm("mov.b64 %0, {%1, %2};" : "=l"(d) : "f"(lo), "f"(hi));
    return d;
}
__device__ __forceinline__ float2 unpack2(unsigned long long v) {
    float lo, hi;
    asm("mov.b64 {%0, %1}, %2;" : "=f"(lo), "=f"(hi) : "l"(v));
    return make_float2(lo, hi);
}

__global__ void __launch_bounds__(NTHREADS)
hybrid_mlp_kernel(const float* __restrict__ x_q,
                  const float* __restrict__ x_c,
                  const float* __restrict__ q_params,
                  const float* __restrict__ w1,
                  const float* __restrict__ b1,
                  const float* __restrict__ w2,
                  const float* __restrict__ b2,
                  const float* __restrict__ w3,
                  const float* __restrict__ b3,
                  float* __restrict__ out,
                  int B) {
    __shared__ __align__(16) float sh_x[ROWS_PER_BLOCK * 63];   // 31.5 KB
    __shared__ __align__(16) float sh_w1[64 * 32];              // [f][o], 8 KB
    __shared__ __align__(16) float sh_w2[32 * 16];              // [k][o], 2 KB
    __shared__ __align__(16) float sh_b1[32];
    __shared__ __align__(16) float sh_b2[16];
    __shared__ __align__(16) float sh_w3[16];

    const int tid = threadIdx.x;
    const long long R0 = (long long)blockIdx.x * ROWS_PER_BLOCK;

    // ---- Stage x_c tile: 128 rows * 63 floats, contiguous region.
    // Byte offset R0*63*4 = blk*32256 is 16B-aligned -> pure float4 copy.
    {
        const float4* src = (const float4*)(x_c + R0 * 63);
        float4* dst = (float4*)sh_x;
        const int nvec = (ROWS_PER_BLOCK * 63) / 4;  // 2016
        #pragma unroll
        for (int k = 0; k < 16; k++) {
            int idx = tid + k * NTHREADS;
            if (idx < nvec) dst[idx] = src[idx];
        }
    }
    // ---- Stage transposed weights: sh_w1[f*32+o] = w1[o*64+f]
    for (int e = tid; e < 2048; e += NTHREADS) {
        int o = e >> 6, f = e & 63;
        sh_w1[f * 32 + o] = w1[e];
    }
    // sh_w2[k*16+o] = w2[o*32+k]
    for (int e = tid; e < 512; e += NTHREADS) {
        int o = e >> 5, k = e & 31;
        sh_w2[k * 16 + o] = w2[e];
    }
    if (tid < 32) sh_b1[tid] = b1[tid];
    if (tid < 16) { sh_b2[tid] = b2[tid]; sh_w3[tid] = w3[tid]; }
    __syncthreads();

    const long long r = R0 + tid;
    if (r >= B) return;

    // ---- Quantum feature (analytic): q = cos(xq1+p1)*cos(xq2+p2)
    const float p1 = __ldg(q_params + 1);
    const float p2 = __ldg(q_params + 2);
    const float q = __cosf(x_q[r * 3 + 1] + p1) * __cosf(x_q[r * 3 + 2] + p2);

    // ---- Layer 1: 64 features -> 32 outputs (16 packed f32x2 accumulators)
    unsigned long long acc[16];
    {
        const unsigned long long* bb = (const unsigned long long*)sh_b1;
        #pragma unroll
        for (int p = 0; p < 16; p++) acc[p] = bb[p];
    }
    // feature 0 = q
    {
        const unsigned long long* wrow = (const unsigned long long*)sh_w1;
        unsigned long long xv = pack2(q, q);
        #pragma unroll
        for (int p = 0; p < 16; p++) acc[p] = ffma2(wrow[p], xv, acc[p]);
    }
    // features 1..63 = x_c (shared row stride 63 floats: odd -> conflict-free)
    const float* xr = sh_x + tid * 63;
    #pragma unroll 7
    for (int f = 1; f < 64; f++) {
        float xf = xr[f - 1];
        unsigned long long xv = pack2(xf, xf);
        const unsigned long long* wrow =
            (const unsigned long long*)(sh_w1 + f * 32);
        #pragma unroll
        for (int p = 0; p < 16; p++) acc[p] = ffma2(wrow[p], xv, acc[p]);
    }

    // ---- Bias+ReLU -> h1 scalars
    float h1[32];
    #pragma unroll
    for (int p = 0; p < 16; p++) {
        float2 v = unpack2(acc[p]);
        h1[2 * p]     = fmaxf(v.x, 0.0f);
        h1[2 * p + 1] = fmaxf(v.y, 0.0f);
    }

    // ---- Layer 2: 32 -> 16 (8 packed accumulators)
    unsigned long long acc2[8];
    {
        const unsigned long long* bb = (const unsigned long long*)sh_b2;
        #pragma unroll
        for (int p = 0; p < 8; p++) acc2[p] = bb[p];
    }
    #pragma unroll
    for (int k = 0; k < 32; k++) {
        unsigned long long xv = pack2(h1[k], h1[k]);
        const unsigned long long* wrow =
            (const unsigned long long*)(sh_w2 + k * 16);
        #pragma unroll
        for (int p = 0; p < 8; p++) acc2[p] = ffma2(wrow[p], xv, acc2[p]);
    }

    // ---- Layer 3: 16 -> 1
    float res = __ldg(b3);
    #pragma unroll
    for (int p = 0; p < 8; p++) {
        float2 v = unpack2(acc2[p]);
        res = fmaf(fmaxf(v.x, 0.0f), sh_w3[2 * p], res);
        res = fmaf(fmaxf(v.y, 0.0f), sh_w3[2 * p + 1], res);
    }
    out[r] = res;
}

extern "C" void kernel_launch(void* const* d_in, const int* in_sizes, int n_in,
                              void* d_out, int out_size) {
    const float* x_q      = (const float*)d_in[0];
    const float* x_c      = (const float*)d_in[1];
    const float* q_params = (const float*)d_in[2];
    const float* w1       = (const float*)d_in[3];
    const float* b1       = (const float*)d_in[4];
    const float* w2       = (const float*)d_in[5];
    const float* b2       = (const float*)d_in[6];
    const float* w3       = (const float*)d_in[7];
    const float* b3       = (const float*)d_in[8];
    float* out = (float*)d_out;

    const int B = in_sizes[0] / 3;  // x_q is [B, 3]
    const int grid = (B + ROWS_PER_BLOCK - 1) / ROWS_PER_BLOCK;
    hybrid_mlp_kernel<<<grid, NTHREADS>>>(x_q, x_c, q_params, w1, b1, w2, b2,
                                          w3, b3, out, B);
}